// round 7
// baseline (speedup 1.0000x reference)
#include <cuda_runtime.h>
#include <cuda_bf16.h>
#include <math.h>

// Problem constants
#define MAXN   50000
#define MAXE   850000   // 800000 edges + 50000 self loops
#define FDIM   64       // hidden = out = 64
#define EPS_D  1e-16f
#define NEG_SLOPE 0.2f

// Scratch (device globals; allocation is forbidden)
__device__ __align__(16) float g_xl[MAXN * FDIM];
__device__ __align__(16) float g_xr[MAXN * FDIM];
__device__ __align__(16) float g_h [MAXN * FDIM];
__device__ __align__(16) float g_e [MAXE];
__device__ __align__(16) float g_ex[MAXE];
__device__ __align__(16) float g_max[MAXN];
__device__ __align__(16) float g_den[MAXN];

// ---------------------------------------------------------------------------
// float atomic max via int punning (monotone under both orderings)
__device__ __forceinline__ void atomicMaxFloat(float* addr, float val) {
    if (!signbit(val)) {
        atomicMax((int*)addr, __float_as_int(val));
    } else {
        atomicMin((unsigned int*)addr, __float_as_uint(val));
    }
}

// ---------------------------------------------------------------------------
// Dual GEMM: xl = x @ Wl, xr = x @ Wr.  x:[N,K], W:[K,64].
// Block = 256 threads: c = tid&63 (output col), rr = tid>>6 (0..3), each
// thread-row handles 8 node rows -> 32 rows per block.
__global__ void gemm_dual(const float* __restrict__ x,
                          const float* __restrict__ Wl,
                          const float* __restrict__ Wr,
                          float* __restrict__ xl,
                          float* __restrict__ xr,
                          int N, int K) {
    __shared__ float sx[32 * 128];
    const int c  = threadIdx.x & 63;
    const int rr = threadIdx.x >> 6;
    const int r0 = blockIdx.x * 32;
    const int kv4 = K >> 2;

    // cooperative load of 32 rows of x into shared (float4)
    const float4* x4 = (const float4*)x;
    float4* sx4 = (float4*)sx;
    const int tot4 = 32 * kv4;
    for (int i = threadIdx.x; i < tot4; i += 256) {
        int row = i / kv4;
        int gr  = r0 + row;
        sx4[i] = (gr < N) ? x4[(size_t)gr * kv4 + (i - row * kv4)]
                          : make_float4(0.f, 0.f, 0.f, 0.f);
    }
    __syncthreads();

    float accl[8], accr[8];
#pragma unroll
    for (int j = 0; j < 8; j++) { accl[j] = 0.f; accr[j] = 0.f; }

    for (int k4 = 0; k4 < kv4; k4++) {
        const int kb = k4 * 4;
        float wl0 = Wl[(kb + 0) * 64 + c];
        float wl1 = Wl[(kb + 1) * 64 + c];
        float wl2 = Wl[(kb + 2) * 64 + c];
        float wl3 = Wl[(kb + 3) * 64 + c];
        float wr0 = Wr[(kb + 0) * 64 + c];
        float wr1 = Wr[(kb + 1) * 64 + c];
        float wr2 = Wr[(kb + 2) * 64 + c];
        float wr3 = Wr[(kb + 3) * 64 + c];
#pragma unroll
        for (int j = 0; j < 8; j++) {
            float4 xv = sx4[(rr * 8 + j) * kv4 + k4];
            accl[j] += xv.x * wl0 + xv.y * wl1 + xv.z * wl2 + xv.w * wl3;
            accr[j] += xv.x * wr0 + xv.y * wr1 + xv.z * wr2 + xv.w * wr3;
        }
    }

#pragma unroll
    for (int j = 0; j < 8; j++) {
        int gr = r0 + rr * 8 + j;
        if (gr < N) {
            xl[(size_t)gr * 64 + c] = accl[j];
            xr[(size_t)gr * 64 + c] = accr[j];
        }
    }
}

// ---------------------------------------------------------------------------
// Init per-node state: e_max=-inf, den=0, out[i] = bias[i%64]
__global__ void init_node(float* __restrict__ emax, float* __restrict__ den,
                          float* __restrict__ out, const float* __restrict__ bias,
                          int N) {
    int i = blockIdx.x * blockDim.x + threadIdx.x;
    int tot = N * FDIM;
    if (i < tot) out[i] = bias[i & 63];
    if (i < N) {
        emax[i] = __int_as_float(0xFF800000); // -inf
        den[i]  = 0.f;
    }
}

// ---------------------------------------------------------------------------
// Edge index fetch: int32 edge_index (JAX x64 disabled -> int64 request
// silently becomes int32). Clamp defensively so a wrong dtype model shows up
// as rel_err, not an illegal access.
__device__ __forceinline__ void edge_sd(const int* __restrict__ e0,
                                        const int* __restrict__ e1,
                                        int w, int Ein, int N,
                                        int& s, int& d) {
    if (w < Ein) {
        s = __ldg(e0 + w);
        d = __ldg(e1 + w);
        if ((unsigned)s >= (unsigned)N) s = 0;
        if ((unsigned)d >= (unsigned)N) d = 0;
    } else {
        s = d = w - Ein;   // self loop
    }
}

// ---------------------------------------------------------------------------
// Pass 1: per-edge logit (warp per edge), store e, atomicMax into e_max[dst]
__global__ void edge_logits(const int* __restrict__ e0,
                            const int* __restrict__ e1,
                            const float* __restrict__ xl,
                            const float* __restrict__ xr,
                            const float* __restrict__ att,
                            float* __restrict__ e_out,
                            float* __restrict__ emax,
                            int E, int Ein, int N) {
    int w = (blockIdx.x * blockDim.x + threadIdx.x) >> 5;
    int lane = threadIdx.x & 31;
    if (w >= E) return;
    int s, d;
    edge_sd(e0, e1, w, Ein, N, s, d);
    const float2* a2 = (const float2*)(xl + (size_t)s * 64);
    const float2* b2 = (const float2*)(xr + (size_t)d * 64);
    float2 a = a2[lane];
    float2 b = b2[lane];
    float2 c = ((const float2*)att)[lane];
    float vx = a.x + b.x; vx = vx > 0.f ? vx : NEG_SLOPE * vx;
    float vy = a.y + b.y; vy = vy > 0.f ? vy : NEG_SLOPE * vy;
    float v = vx * c.x + vy * c.y;
#pragma unroll
    for (int off = 16; off; off >>= 1)
        v += __shfl_down_sync(0xffffffffu, v, off);
    if (lane == 0) {
        e_out[w] = v;
        atomicMaxFloat(&emax[d], v);
    }
}

// ---------------------------------------------------------------------------
// Pass 2: ex = exp(e - max[dst]); den[dst] += ex  (thread per edge)
__global__ void edge_exp(const int* __restrict__ e1,
                         const float* __restrict__ e,
                         const float* __restrict__ emax,
                         float* __restrict__ ex,
                         float* __restrict__ den,
                         int E, int Ein, int N) {
    int i = blockIdx.x * blockDim.x + threadIdx.x;
    if (i >= E) return;
    int d;
    if (i < Ein) {
        d = __ldg(e1 + i);
        if ((unsigned)d >= (unsigned)N) d = 0;
    } else {
        d = i - Ein;
    }
    float v = __expf(e[i] - emax[d]);
    ex[i] = v;
    atomicAdd(&den[d], v);
}

// ---------------------------------------------------------------------------
// Pass 3: out[dst] += alpha * xl[src]  (warp per edge, vector red.v2.f32)
__global__ void edge_scatter(const int* __restrict__ e0,
                             const int* __restrict__ e1,
                             const float* __restrict__ xl,
                             const float* __restrict__ ex,
                             const float* __restrict__ den,
                             float* __restrict__ out,
                             int E, int Ein, int N) {
    int w = (blockIdx.x * blockDim.x + threadIdx.x) >> 5;
    int lane = threadIdx.x & 31;
    if (w >= E) return;
    int s, d;
    edge_sd(e0, e1, w, Ein, N, s, d);
    float alpha = ex[w] / (den[d] + EPS_D);
    const float2* a2 = (const float2*)(xl + (size_t)s * 64);
    float2 a = a2[lane];
    float* p = out + (size_t)d * 64 + lane * 2;
    float ax = alpha * a.x;
    float ay = alpha * a.y;
    asm volatile("red.global.add.v2.f32 [%0], {%1, %2};"
                 :: "l"(p), "f"(ax), "f"(ay) : "memory");
}

// ---------------------------------------------------------------------------
__global__ void relu_kernel(float* __restrict__ h, int n) {
    int i = blockIdx.x * blockDim.x + threadIdx.x;
    if (i < n) h[i] = fmaxf(h[i], 0.f);
}

// ---------------------------------------------------------------------------
extern "C" void kernel_launch(void* const* d_in, const int* in_sizes, int n_in,
                              void* d_out, int out_size) {
    const float* x    = (const float*)d_in[0];
    const int*   ei   = (const int*)d_in[1];    // int32! (JAX x64 disabled)
    const float* W1l  = (const float*)d_in[2];
    const float* W1r  = (const float*)d_in[3];
    const float* att1 = (const float*)d_in[4];
    const float* b1   = (const float*)d_in[5];
    const float* W2l  = (const float*)d_in[6];
    const float* W2r  = (const float*)d_in[7];
    const float* att2 = (const float*)d_in[8];
    const float* b2   = (const float*)d_in[9];
    float*       out  = (float*)d_out;

    const int N   = in_sizes[0] / 128;   // 50000
    const int Ein = in_sizes[1] / 2;     // 800000
    const int E   = Ein + N;             // 850000 (self loops appended)

    float *xl, *xr, *h, *e, *exb, *mx, *den;
    cudaGetSymbolAddress((void**)&xl,  g_xl);
    cudaGetSymbolAddress((void**)&xr,  g_xr);
    cudaGetSymbolAddress((void**)&h,   g_h);
    cudaGetSymbolAddress((void**)&e,   g_e);
    cudaGetSymbolAddress((void**)&exb, g_ex);
    cudaGetSymbolAddress((void**)&mx,  g_max);
    cudaGetSymbolAddress((void**)&den, g_den);

    const int* e0 = ei;         // edge_index[0] : src
    const int* e1 = ei + Ein;   // edge_index[1] : dst

    const int gB   = (N + 31) / 32;            // gemm blocks
    const int nB   = (N * FDIM + 255) / 256;   // per-node-feature blocks
    const int ewB  = (E * 32 + 255) / 256;     // warp-per-edge blocks
    const int etB  = (E + 255) / 256;          // thread-per-edge blocks

    // ------------- Layer 1 -------------
    gemm_dual<<<gB, 256>>>(x, W1l, W1r, xl, xr, N, 128);
    init_node<<<nB, 256>>>(mx, den, h, b1, N);
    edge_logits<<<ewB, 256>>>(e0, e1, xl, xr, att1, e, mx, E, Ein, N);
    edge_exp<<<etB, 256>>>(e1, e, mx, exb, den, E, Ein, N);
    edge_scatter<<<ewB, 256>>>(e0, e1, xl, exb, den, h, E, Ein, N);
    relu_kernel<<<nB, 256>>>(h, N * FDIM);

    // ------------- Layer 2 -------------
    gemm_dual<<<gB, 256>>>(h, W2l, W2r, xl, xr, N, 64);
    init_node<<<nB, 256>>>(mx, den, out, b2, N);
    edge_logits<<<ewB, 256>>>(e0, e1, xl, xr, att2, e, mx, E, Ein, N);
    edge_exp<<<etB, 256>>>(e1, e, mx, exb, den, E, Ein, N);
    edge_scatter<<<ewB, 256>>>(e0, e1, xl, exb, den, out, E, Ein, N);
}

// round 9
// speedup vs baseline: 1.6480x; 1.6480x over previous
#include <cuda_runtime.h>
#include <cuda_bf16.h>
#include <math.h>

// Problem constants
#define MAXN   50000
#define MAXE   850000   // 800000 edges + 50000 self loops
#define FDIM   64
#define EPS_D  1e-16f
#define NEG_SLOPE 0.2f

// Scratch (device globals; allocation is forbidden)
__device__ __align__(16) float g_xl[MAXN * FDIM];
__device__ __align__(16) float g_xr[MAXN * FDIM];
__device__ __align__(16) float g_h [MAXN * FDIM];
__device__ int g_cnt[MAXN];
__device__ int g_off[MAXN + 1];
__device__ int g_cur[MAXN];
__device__ int g_csr[MAXE];

// ---------------------------------------------------------------------------
// Dual GEMM: xl = x @ Wl, xr = x @ Wr.  x:[N,K], W:[K,64].
__global__ void gemm_dual(const float* __restrict__ x,
                          const float* __restrict__ Wl,
                          const float* __restrict__ Wr,
                          float* __restrict__ xl,
                          float* __restrict__ xr,
                          int N, int K) {
    __shared__ float sx[32 * 128];
    const int c  = threadIdx.x & 63;
    const int rr = threadIdx.x >> 6;
    const int r0 = blockIdx.x * 32;
    const int kv4 = K >> 2;

    const float4* x4 = (const float4*)x;
    float4* sx4 = (float4*)sx;
    const int tot4 = 32 * kv4;
    for (int i = threadIdx.x; i < tot4; i += 256) {
        int row = i / kv4;
        int gr  = r0 + row;
        sx4[i] = (gr < N) ? x4[(size_t)gr * kv4 + (i - row * kv4)]
                          : make_float4(0.f, 0.f, 0.f, 0.f);
    }
    __syncthreads();

    float accl[8], accr[8];
#pragma unroll
    for (int j = 0; j < 8; j++) { accl[j] = 0.f; accr[j] = 0.f; }

    for (int k4 = 0; k4 < kv4; k4++) {
        const int kb = k4 * 4;
        float wl0 = Wl[(kb + 0) * 64 + c];
        float wl1 = Wl[(kb + 1) * 64 + c];
        float wl2 = Wl[(kb + 2) * 64 + c];
        float wl3 = Wl[(kb + 3) * 64 + c];
        float wr0 = Wr[(kb + 0) * 64 + c];
        float wr1 = Wr[(kb + 1) * 64 + c];
        float wr2 = Wr[(kb + 2) * 64 + c];
        float wr3 = Wr[(kb + 3) * 64 + c];
#pragma unroll
        for (int j = 0; j < 8; j++) {
            float4 xv = sx4[(rr * 8 + j) * kv4 + k4];
            accl[j] += xv.x * wl0 + xv.y * wl1 + xv.z * wl2 + xv.w * wl3;
            accr[j] += xv.x * wr0 + xv.y * wr1 + xv.z * wr2 + xv.w * wr3;
        }
    }

#pragma unroll
    for (int j = 0; j < 8; j++) {
        int gr = r0 + rr * 8 + j;
        if (gr < N) {
            xl[(size_t)gr * 64 + c] = accl[j];
            xr[(size_t)gr * 64 + c] = accr[j];
        }
    }
}

// ---------------------------------------------------------------------------
// CSR build: counts (seeded with 1 for the self loop)
__global__ void init_counts(int* __restrict__ cnt, int N) {
    int i = blockIdx.x * blockDim.x + threadIdx.x;
    if (i < N) cnt[i] = 1;
}

__global__ void hist_dst(const int* __restrict__ e1, int* __restrict__ cnt,
                         int Ein, int N) {
    int i = blockIdx.x * blockDim.x + threadIdx.x;
    if (i >= Ein) return;
    int d = __ldg(e1 + i);
    if ((unsigned)d >= (unsigned)N) d = 0;
    atomicAdd(&cnt[d], 1);
}

// Single-block exclusive scan over N counts -> off[0..N], cur[i]=off[i]
__global__ void scan_counts(const int* __restrict__ cnt,
                            int* __restrict__ off,
                            int* __restrict__ cur, int N) {
    const int T = 1024;
    int t = threadIdx.x;
    int C = (N + T - 1) / T;
    int lo = t * C;
    int hi = lo + C; if (hi > N) hi = N; if (lo > N) lo = N;

    int sum = 0;
    for (int i = lo; i < hi; i++) sum += cnt[i];

    __shared__ int wsum[32];
    int lane = t & 31, wid = t >> 5;
    int v = sum;
#pragma unroll
    for (int o = 1; o < 32; o <<= 1) {
        int u = __shfl_up_sync(0xffffffffu, v, o);
        if (lane >= o) v += u;
    }
    if (lane == 31) wsum[wid] = v;
    __syncthreads();
    if (wid == 0) {
        int ws = wsum[lane];
#pragma unroll
        for (int o = 1; o < 32; o <<= 1) {
            int u = __shfl_up_sync(0xffffffffu, ws, o);
            if (lane >= o) ws += u;
        }
        wsum[lane] = ws;
    }
    __syncthreads();
    int excl = v - sum + (wid > 0 ? wsum[wid - 1] : 0);

    int run = excl;
    for (int i = lo; i < hi; i++) {
        off[i] = run;
        cur[i] = run;
        run += cnt[i];
    }
    if (hi == N) off[N] = run;   // all threads with hi==N write total
}

// Scatter edges (and self loops) into CSR by dst
__global__ void csr_scatter(const int* __restrict__ e0,
                            const int* __restrict__ e1,
                            int* __restrict__ cur,
                            int* __restrict__ csr,
                            int Ein, int E, int N) {
    int i = blockIdx.x * blockDim.x + threadIdx.x;
    if (i >= E) return;
    int s, d;
    if (i < Ein) {
        s = __ldg(e0 + i);
        d = __ldg(e1 + i);
        if ((unsigned)s >= (unsigned)N) s = 0;
        if ((unsigned)d >= (unsigned)N) d = 0;
    } else {
        s = d = i - Ein;   // self loop
    }
    int pos = atomicAdd(&cur[d], 1);
    csr[pos] = s;
}

// ---------------------------------------------------------------------------
// Fused GATv2 edge phase: warp per dst node.
// out[d] = (sum_e exp(e)*xl[src_e]) / (sum_e exp(e) + eps) + bias  [+ relu]
// (max-subtraction dropped: |logit| <~ 5, exp safe; normalization cancels it)
__global__ void gat_fused(const int* __restrict__ csr,
                          const int* __restrict__ off,
                          const float* __restrict__ xl,
                          const float* __restrict__ xr,
                          const float* __restrict__ att,
                          const float* __restrict__ bias,
                          float* __restrict__ out,
                          int N, int do_relu) {
    int w    = (blockIdx.x * blockDim.x + threadIdx.x) >> 5;
    int lane = threadIdx.x & 31;
    if (w >= N) return;

    const float2* xl2 = (const float2*)xl;
    float2 b = __ldg((const float2*)(xr) + (size_t)w * 32 + lane);
    float2 c = __ldg((const float2*)att + lane);

    int k0 = __ldg(off + w);
    int k1 = __ldg(off + w + 1);

    float accx = 0.f, accy = 0.f, den = 0.f;

    for (int k = k0; k < k1; k += 4) {
        int n = k1 - k;                       // >= 1
        int s0 = __ldg(csr + k);
        int s1 = (n > 1) ? __ldg(csr + k + 1) : s0;
        int s2 = (n > 2) ? __ldg(csr + k + 2) : s0;
        int s3 = (n > 3) ? __ldg(csr + k + 3) : s0;

        float2 a0 = __ldg(xl2 + (size_t)s0 * 32 + lane);
        float2 a1 = __ldg(xl2 + (size_t)s1 * 32 + lane);
        float2 a2 = __ldg(xl2 + (size_t)s2 * 32 + lane);
        float2 a3 = __ldg(xl2 + (size_t)s3 * 32 + lane);

        float t, v0, v1, v2, v3;
        t = a0.x + b.x; t = t > 0.f ? t : NEG_SLOPE * t; v0  = t * c.x;
        t = a0.y + b.y; t = t > 0.f ? t : NEG_SLOPE * t; v0 += t * c.y;
        t = a1.x + b.x; t = t > 0.f ? t : NEG_SLOPE * t; v1  = t * c.x;
        t = a1.y + b.y; t = t > 0.f ? t : NEG_SLOPE * t; v1 += t * c.y;
        t = a2.x + b.x; t = t > 0.f ? t : NEG_SLOPE * t; v2  = t * c.x;
        t = a2.y + b.y; t = t > 0.f ? t : NEG_SLOPE * t; v2 += t * c.y;
        t = a3.x + b.x; t = t > 0.f ? t : NEG_SLOPE * t; v3  = t * c.x;
        t = a3.y + b.y; t = t > 0.f ? t : NEG_SLOPE * t; v3 += t * c.y;

#pragma unroll
        for (int o = 16; o; o >>= 1) {
            v0 += __shfl_xor_sync(0xffffffffu, v0, o);
            v1 += __shfl_xor_sync(0xffffffffu, v1, o);
            v2 += __shfl_xor_sync(0xffffffffu, v2, o);
            v3 += __shfl_xor_sync(0xffffffffu, v3, o);
        }

        float ex0 = __expf(v0);
        float ex1 = (n > 1) ? __expf(v1) : 0.f;
        float ex2 = (n > 2) ? __expf(v2) : 0.f;
        float ex3 = (n > 3) ? __expf(v3) : 0.f;

        den  += (ex0 + ex1) + (ex2 + ex3);
        accx += ex0 * a0.x + ex1 * a1.x + ex2 * a2.x + ex3 * a3.x;
        accy += ex0 * a0.y + ex1 * a1.y + ex2 * a2.y + ex3 * a3.y;
    }

    float inv = 1.f / (den + EPS_D);
    float ox = accx * inv + __ldg(bias + lane * 2);
    float oy = accy * inv + __ldg(bias + lane * 2 + 1);
    if (do_relu) { ox = fmaxf(ox, 0.f); oy = fmaxf(oy, 0.f); }
    ((float2*)out)[(size_t)w * 32 + lane] = make_float2(ox, oy);
}

// ---------------------------------------------------------------------------
extern "C" void kernel_launch(void* const* d_in, const int* in_sizes, int n_in,
                              void* d_out, int out_size) {
    const float* x    = (const float*)d_in[0];
    const int*   ei   = (const int*)d_in[1];    // int32 (JAX x64 disabled)
    const float* W1l  = (const float*)d_in[2];
    const float* W1r  = (const float*)d_in[3];
    const float* att1 = (const float*)d_in[4];
    const float* b1   = (const float*)d_in[5];
    const float* W2l  = (const float*)d_in[6];
    const float* W2r  = (const float*)d_in[7];
    const float* att2 = (const float*)d_in[8];
    const float* b2   = (const float*)d_in[9];
    float*       out  = (float*)d_out;

    const int N   = in_sizes[0] / 128;   // 50000
    const int Ein = in_sizes[1] / 2;     // 800000
    const int E   = Ein + N;             // 850000

    float *xl, *xr, *h;
    int *cnt, *off, *cur, *csr;
    cudaGetSymbolAddress((void**)&xl,  g_xl);
    cudaGetSymbolAddress((void**)&xr,  g_xr);
    cudaGetSymbolAddress((void**)&h,   g_h);
    cudaGetSymbolAddress((void**)&cnt, g_cnt);
    cudaGetSymbolAddress((void**)&off, g_off);
    cudaGetSymbolAddress((void**)&cur, g_cur);
    cudaGetSymbolAddress((void**)&csr, g_csr);

    const int* e0 = ei;         // src
    const int* e1 = ei + Ein;   // dst

    const int gB  = (N + 31) / 32;
    const int nB  = (N + 255) / 256;
    const int eB  = (Ein + 255) / 256;
    const int aB  = (E + 255) / 256;
    const int fB  = (N * 32 + 255) / 256;  // warp per dst, 8 warps/block

    // ---- CSR build (shared by both layers) ----
    init_counts<<<nB, 256>>>(cnt, N);
    hist_dst<<<eB, 256>>>(e1, cnt, Ein, N);
    scan_counts<<<1, 1024>>>(cnt, off, cur, N);
    csr_scatter<<<aB, 256>>>(e0, e1, cur, csr, Ein, E, N);

    // ---- Layer 1 ----
    gemm_dual<<<gB, 256>>>(x, W1l, W1r, xl, xr, N, 128);
    gat_fused<<<fB, 256>>>(csr, off, xl, xr, att1, b1, h, N, 1);

    // ---- Layer 2 ----
    gemm_dual<<<gB, 256>>>(h, W2l, W2r, xl, xr, N, 64);
    gat_fused<<<fB, 256>>>(csr, off, xl, xr, att2, b2, out, N, 0);
}